// round 1
// baseline (speedup 1.0000x reference)
#include <cuda_runtime.h>
#include <math.h>

#define SEQ  2048
#define DM   1024
#define TDM  3072
#define NH   16
#define DH   64
#define MAXD 128

// Scratch (allocation-free rule: __device__ globals)
__device__ float g_qkv[SEQ * TDM];   // [s][3*d_model]
__device__ float g_attn[SEQ * DM];   // [s][h*64+d]

// ---------------------------------------------------------------------------
// Tiled fp32 GEMM: C[M,N] = A[M,K] @ B[K,N].  BM=BN=64, BK=16, 256 threads,
// 4x4 micro-tile per thread. M,N,K must be multiples of 64/64/16 (they are).
// ---------------------------------------------------------------------------
__global__ __launch_bounds__(256)
void gemm_tiled(const float* __restrict__ A, const float* __restrict__ B,
                float* __restrict__ C, int M, int N, int K) {
    __shared__ float As[16][64];   // As[k][m] (transposed)
    __shared__ float Bs[16][64];   // Bs[k][n]

    const int tid = threadIdx.x;
    const int tx = tid & 15;       // n sub-tile
    const int ty = tid >> 4;       // m sub-tile
    const int bm = blockIdx.y * 64;
    const int bn = blockIdx.x * 64;

    const int arow = tid >> 2;           // 0..63
    const int ac4  = (tid & 3) << 2;     // 0,4,8,12
    const int brow = tid >> 4;           // 0..15
    const int bc4  = (tid & 15) << 2;    // 0..60

    float acc[4][4];
#pragma unroll
    for (int i = 0; i < 4; i++)
#pragma unroll
        for (int j = 0; j < 4; j++) acc[i][j] = 0.f;

    for (int kb = 0; kb < K; kb += 16) {
        float4 av = *(const float4*)&A[(bm + arow) * K + kb + ac4];
        float4 bv = *(const float4*)&B[(kb + brow) * N + bn + bc4];
        As[ac4 + 0][arow] = av.x;
        As[ac4 + 1][arow] = av.y;
        As[ac4 + 2][arow] = av.z;
        As[ac4 + 3][arow] = av.w;
        *(float4*)&Bs[brow][bc4] = bv;
        __syncthreads();

#pragma unroll
        for (int k = 0; k < 16; k++) {
            float a[4], b[4];
            *(float4*)a = *(const float4*)&As[k][ty * 4];
            *(float4*)b = *(const float4*)&Bs[k][tx * 4];
#pragma unroll
            for (int i = 0; i < 4; i++)
#pragma unroll
                for (int j = 0; j < 4; j++)
                    acc[i][j] = fmaf(a[i], b[j], acc[i][j]);
        }
        __syncthreads();
    }

#pragma unroll
    for (int i = 0; i < 4; i++) {
        float4 o = make_float4(acc[i][0], acc[i][1], acc[i][2], acc[i][3]);
        *(float4*)&C[(bm + ty * 4 + i) * N + bn + tx * 4] = o;
    }
}

// ---------------------------------------------------------------------------
// Flash attention with relative-position bias.
// Grid: (SEQ/64, NH). Block: 256 threads (tx 0..15 = key/dim cols, ty = q rows).
// Per block: Q tile [64 x 64] resident in smem; loop over 32 key tiles of 64.
// Smem (dynamic): Qs[64][68], Kt[64][68] (K transposed; reused as P), Vs[64][68].
// ---------------------------------------------------------------------------
#define ATTN_STRIDE 68
#define ATTN_SMEM   (3 * 64 * ATTN_STRIDE * 4)

__global__ __launch_bounds__(256)
void attn_kernel(const float* __restrict__ qkv, const float* __restrict__ rel_bias,
                 float* __restrict__ out) {
    extern __shared__ float sm[];
    float (*Qs)[ATTN_STRIDE] = (float(*)[ATTN_STRIDE])sm;
    float (*Kt)[ATTN_STRIDE] = (float(*)[ATTN_STRIDE])(sm + 64 * ATTN_STRIDE);     // Kt[d][key]; aliased as P[row][key]
    float (*Vs)[ATTN_STRIDE] = (float(*)[ATTN_STRIDE])(sm + 2 * 64 * ATTN_STRIDE); // Vs[key][d]
    __shared__ float bias_s[MAXD];

    const int tid = threadIdx.x;
    const int tx = tid & 15;
    const int ty = tid >> 4;
    const int h  = blockIdx.y;
    const int q0 = blockIdx.x * 64;

    if (tid < MAXD) bias_s[tid] = rel_bias[tid * NH + h];

    const int lrow = tid >> 4;          // 0..15
    const int lc4  = (tid & 15) << 2;   // 0..60

    // Load Q tile (64 rows x 64 dims) for this head
#pragma unroll
    for (int p = 0; p < 4; p++) {
        int r = lrow + p * 16;
        float4 v = *(const float4*)&qkv[(q0 + r) * TDM + h * DH + lc4];
        *(float4*)&Qs[r][lc4] = v;
    }

    float m_i[4], l_i[4], accO[4][4];
#pragma unroll
    for (int i = 0; i < 4; i++) {
        m_i[i] = -1e30f;
        l_i[i] = 0.f;
#pragma unroll
        for (int j = 0; j < 4; j++) accO[i][j] = 0.f;
    }
    __syncthreads();

    for (int kt = 0; kt < SEQ / 64; kt++) {
        const int k0 = kt * 64;
        // Load K (transposed into Kt[d][key]) and V (Vs[key][d])
#pragma unroll
        for (int p = 0; p < 4; p++) {
            int r = lrow + p * 16;
            float4 kv = *(const float4*)&qkv[(k0 + r) * TDM + DM + h * DH + lc4];
            Kt[lc4 + 0][r] = kv.x;
            Kt[lc4 + 1][r] = kv.y;
            Kt[lc4 + 2][r] = kv.z;
            Kt[lc4 + 3][r] = kv.w;
            float4 vv = *(const float4*)&qkv[(k0 + r) * TDM + 2 * DM + h * DH + lc4];
            *(float4*)&Vs[r][lc4] = vv;
        }
        __syncthreads();

        // S = Q K^T  (4x4 per thread)
        float s[4][4];
#pragma unroll
        for (int i = 0; i < 4; i++)
#pragma unroll
            for (int j = 0; j < 4; j++) s[i][j] = 0.f;

#pragma unroll 4
        for (int d = 0; d < DH; d++) {
            float qv[4];
#pragma unroll
            for (int i = 0; i < 4; i++) qv[i] = Qs[ty * 4 + i][d];
            float kv[4];
            *(float4*)kv = *(const float4*)&Kt[d][tx * 4];
#pragma unroll
            for (int i = 0; i < 4; i++)
#pragma unroll
                for (int j = 0; j < 4; j++)
                    s[i][j] = fmaf(qv[i], kv[j], s[i][j]);
        }

        // scale + relative bias
#pragma unroll
        for (int i = 0; i < 4; i++) {
            int qg = q0 + ty * 4 + i;
#pragma unroll
            for (int j = 0; j < 4; j++) {
                int kg = k0 + tx * 4 + j;
                int dd = kg - qg;
                dd = dd < 0 ? -dd : dd;
                if (dd > MAXD - 1) dd = MAXD - 1;
                s[i][j] = fmaf(s[i][j], 0.125f, bias_s[dd]);
            }
        }

        // online softmax: row max (reduce over 16 tx lanes), rescale, exp, row sum
        float fac[4];
#pragma unroll
        for (int i = 0; i < 4; i++) {
            float mx = fmaxf(fmaxf(s[i][0], s[i][1]), fmaxf(s[i][2], s[i][3]));
#pragma unroll
            for (int o = 8; o >= 1; o >>= 1)
                mx = fmaxf(mx, __shfl_xor_sync(0xffffffffu, mx, o));
            float mnew = fmaxf(m_i[i], mx);
            fac[i] = __expf(m_i[i] - mnew);
            m_i[i] = mnew;
        }
#pragma unroll
        for (int i = 0; i < 4; i++) {
            float sum = 0.f;
#pragma unroll
            for (int j = 0; j < 4; j++) {
                s[i][j] = __expf(s[i][j] - m_i[i]);
                sum += s[i][j];
            }
#pragma unroll
            for (int o = 8; o >= 1; o >>= 1)
                sum += __shfl_xor_sync(0xffffffffu, sum, o);
            l_i[i] = l_i[i] * fac[i] + sum;
#pragma unroll
            for (int j = 0; j < 4; j++) accO[i][j] *= fac[i];
        }

        __syncthreads();   // everyone done reading Kt before we alias it as P
#pragma unroll
        for (int i = 0; i < 4; i++)
#pragma unroll
            for (int j = 0; j < 4; j++)
                Kt[ty * 4 + i][tx * 4 + j] = s[i][j];   // P[row][key]
        __syncthreads();

        // O += P V  (thread owns rows ty*4+i, dims tx*4+j)
#pragma unroll 4
        for (int j = 0; j < 64; j++) {
            float vv[4];
            *(float4*)vv = *(const float4*)&Vs[j][tx * 4];
#pragma unroll
            for (int i = 0; i < 4; i++) {
                float p = Kt[ty * 4 + i][j];
#pragma unroll
                for (int c = 0; c < 4; c++)
                    accO[i][c] = fmaf(p, vv[c], accO[i][c]);
            }
        }
        __syncthreads();   // before next tile overwrites Kt/Vs
    }

    // epilogue: normalize and write [s][h*64+d]
#pragma unroll
    for (int i = 0; i < 4; i++) {
        float inv = 1.f / l_i[i];
        float4 o = make_float4(accO[i][0] * inv, accO[i][1] * inv,
                               accO[i][2] * inv, accO[i][3] * inv);
        *(float4*)&out[(q0 + ty * 4 + i) * DM + h * DH + tx * 4] = o;
    }
}

// ---------------------------------------------------------------------------
extern "C" void kernel_launch(void* const* d_in, const int* in_sizes, int n_in,
                              void* d_out, int out_size) {
    const float* x        = (const float*)d_in[0];
    const float* w_qkv    = (const float*)d_in[1];
    const float* w_out    = (const float*)d_in[2];
    const float* rel_bias = (const float*)d_in[3];
    float* out = (float*)d_out;

    float *qkv = nullptr, *attn = nullptr;
    cudaGetSymbolAddress((void**)&qkv,  g_qkv);
    cudaGetSymbolAddress((void**)&attn, g_attn);

    cudaFuncSetAttribute(attn_kernel, cudaFuncAttributeMaxDynamicSharedMemorySize,
                         ATTN_SMEM);

    // 1) qkv = x @ w_qkv   [2048,1024]x[1024,3072]
    gemm_tiled<<<dim3(TDM / 64, SEQ / 64), 256>>>(x, w_qkv, qkv, SEQ, TDM, DM);

    // 2) attention per (q-tile, head)
    attn_kernel<<<dim3(SEQ / 64, NH), 256, ATTN_SMEM>>>(qkv, rel_bias, attn);

    // 3) out = attn @ w_out  [2048,1024]x[1024,1024]
    gemm_tiled<<<dim3(DM / 64, SEQ / 64), 256>>>(attn, w_out, out, SEQ, DM, DM);
}

// round 3
// speedup vs baseline: 1.1408x; 1.1408x over previous
#include <cuda_runtime.h>
#include <cstdint>
#include <math.h>

#define SEQ  2048
#define DM   1024
#define TDM  3072
#define NH   16
#define DH   64
#define MAXD 128

typedef unsigned long long ull;

// ---------------- scratch ---------------------------------------------------
__device__ float g_qkv[SEQ * TDM];   // [s][3*d_model]
__device__ float g_attn[SEQ * DM];   // [s][h*64+d]

// ---------------- f32x2 helpers ---------------------------------------------
__device__ __forceinline__ ull pk2(float x, float y) {
    ull d;
    asm("mov.b64 %0, {%1, %2};" : "=l"(d) : "f"(x), "f"(y));
    return d;
}
__device__ __forceinline__ void upk2(ull d, float& x, float& y) {
    asm("mov.b64 {%0, %1}, %2;" : "=f"(x), "=f"(y) : "l"(d));
}
#define FMA2(c, a, b) asm("fma.rn.f32x2 %0, %1, %2, %0;" : "+l"(c) : "l"(a), "l"(b))
#define MUL2(c, a)    asm("mul.rn.f32x2 %0, %0, %1;"     : "+l"(c) : "l"(a))

// ---------------------------------------------------------------------------
// FFMA2 GEMM: C[M,N] = A[M,K] @ B[K,N].  BM=BN=128, BK=16, 256 threads,
// 8x8 micro-tile per thread (held as 4x8 f32x2 pairs along M).
// Register-staged double buffering for gmem loads.
// ---------------------------------------------------------------------------
__global__ __launch_bounds__(256, 2)
void gemm_f2(const float* __restrict__ A, const float* __restrict__ B,
             float* __restrict__ C, int M, int N, int K) {
    __shared__ float As[16][132];   // As[k][m] transposed, padded
    __shared__ float Bs[16][128];   // Bs[k][n]

    const int tid = threadIdx.x;
    const int tx = tid & 15;        // n: 8 cols at tx*8
    const int ty = tid >> 4;        // m: 8 rows at ty*8
    const int bm = blockIdx.y * 128;
    const int bn = blockIdx.x * 128;

    const int ar = tid >> 2;            // 0..63 (rows ar, ar+64)
    const int ac = (tid & 3) << 2;      // k cols 0,4,8,12
    const int br = tid >> 5;            // 0..7 (k rows br, br+8)
    const int bc = (tid & 31) << 2;     // n cols

    const float* Aptr = A + (bm + ar) * K + ac;
    const float* Bptr = B + br * N + bn + bc;

    float4 a0 = *(const float4*)(Aptr);
    float4 a1 = *(const float4*)(Aptr + 64 * K);
    float4 b0 = *(const float4*)(Bptr);
    float4 b1 = *(const float4*)(Bptr + 8 * N);

    ull acc[4][8];
#pragma unroll
    for (int p = 0; p < 4; p++)
#pragma unroll
        for (int j = 0; j < 8; j++) acc[p][j] = 0ull;

    const int NT = K / 16;
    for (int t = 0; t < NT; t++) {
        // stage -> smem
        As[ac + 0][ar] = a0.x; As[ac + 1][ar] = a0.y;
        As[ac + 2][ar] = a0.z; As[ac + 3][ar] = a0.w;
        As[ac + 0][ar + 64] = a1.x; As[ac + 1][ar + 64] = a1.y;
        As[ac + 2][ar + 64] = a1.z; As[ac + 3][ar + 64] = a1.w;
        *(float4*)&Bs[br][bc]     = b0;
        *(float4*)&Bs[br + 8][bc] = b1;
        __syncthreads();

        if (t + 1 < NT) {   // prefetch next tile into regs (overlaps compute)
            a0 = *(const float4*)(Aptr + (t + 1) * 16);
            a1 = *(const float4*)(Aptr + (t + 1) * 16 + 64 * K);
            b0 = *(const float4*)(Bptr + (t + 1) * 16 * N);
            b1 = *(const float4*)(Bptr + (t + 1) * 16 * N + 8 * N);
        }

#pragma unroll
        for (int k = 0; k < 16; k++) {
            float4 qa0 = *(const float4*)&As[k][ty * 8];
            float4 qa1 = *(const float4*)&As[k][ty * 8 + 4];
            float4 qb0 = *(const float4*)&Bs[k][tx * 8];
            float4 qb1 = *(const float4*)&Bs[k][tx * 8 + 4];
            ull a2[4];
            a2[0] = pk2(qa0.x, qa0.y); a2[1] = pk2(qa0.z, qa0.w);
            a2[2] = pk2(qa1.x, qa1.y); a2[3] = pk2(qa1.z, qa1.w);
            ull bd[8];
            bd[0] = pk2(qb0.x, qb0.x); bd[1] = pk2(qb0.y, qb0.y);
            bd[2] = pk2(qb0.z, qb0.z); bd[3] = pk2(qb0.w, qb0.w);
            bd[4] = pk2(qb1.x, qb1.x); bd[5] = pk2(qb1.y, qb1.y);
            bd[6] = pk2(qb1.z, qb1.z); bd[7] = pk2(qb1.w, qb1.w);
#pragma unroll
            for (int p = 0; p < 4; p++)
#pragma unroll
                for (int j = 0; j < 8; j++)
                    FMA2(acc[p][j], a2[p], bd[j]);
        }
        __syncthreads();
    }

    // epilogue: unpack pairs (rows 2p, 2p+1) and store coalesced
#pragma unroll
    for (int p = 0; p < 4; p++) {
        float lo[8], hi[8];
#pragma unroll
        for (int j = 0; j < 8; j++) upk2(acc[p][j], lo[j], hi[j]);
        const int r0 = bm + ty * 8 + 2 * p;
        float* c0 = &C[(ull)r0 * N + bn + tx * 8];
        float* c1 = c0 + N;
        *(float4*)(c0)     = make_float4(lo[0], lo[1], lo[2], lo[3]);
        *(float4*)(c0 + 4) = make_float4(lo[4], lo[5], lo[6], lo[7]);
        *(float4*)(c1)     = make_float4(hi[0], hi[1], hi[2], hi[3]);
        *(float4*)(c1 + 4) = make_float4(hi[4], hi[5], hi[6], hi[7]);
    }
}

// ---------------------------------------------------------------------------
// Flash attention with relative-position bias, FFMA2 inner loops.
// Grid: (SEQ/64, NH). Block 256 (tx 0..15, ty 0..15), 4x4 per thread
// (rows paired into f32x2). Q and P stored transposed in smem so the
// row-dimension operand loads are contiguous pairs.
// ---------------------------------------------------------------------------
#define AST 68
#define ATTN_SMEM (3 * 64 * AST * 4)

__global__ __launch_bounds__(256, 2)
void attn_kernel(const float* __restrict__ qkv, const float* __restrict__ rel_bias,
                 float* __restrict__ out) {
    extern __shared__ float sm[];
    float (*Qt)[AST] = (float(*)[AST])sm;                   // Qt[d][row]
    float (*Kt)[AST] = (float(*)[AST])(sm + 64 * AST);      // Kt[d][key]; aliased Pt[key][row]
    float (*Vs)[AST] = (float(*)[AST])(sm + 2 * 64 * AST);  // Vs[key][d]
    __shared__ float bias_s[MAXD];

    const int tid = threadIdx.x;
    const int tx = tid & 15;
    const int ty = tid >> 4;
    const int h  = blockIdx.y;
    const int q0 = blockIdx.x * 64;

    if (tid < MAXD) bias_s[tid] = rel_bias[tid * NH + h];

    const int lrow = tid >> 4;
    const int lc4  = (tid & 15) << 2;

    // Q tile -> transposed smem
#pragma unroll
    for (int p = 0; p < 4; p++) {
        const int r = lrow + p * 16;
        float4 v = *(const float4*)&qkv[(q0 + r) * TDM + h * DH + lc4];
        Qt[lc4 + 0][r] = v.x; Qt[lc4 + 1][r] = v.y;
        Qt[lc4 + 2][r] = v.z; Qt[lc4 + 3][r] = v.w;
    }

    // prologue: stage K/V tile 0 into registers
    float4 kreg[4], vreg[4];
#pragma unroll
    for (int p = 0; p < 4; p++) {
        const int r = lrow + p * 16;
        kreg[p] = *(const float4*)&qkv[r * TDM + DM + h * DH + lc4];
        vreg[p] = *(const float4*)&qkv[r * TDM + 2 * DM + h * DH + lc4];
    }

    float m_i[4], l_i[4];
    ull accO2[2][4];
#pragma unroll
    for (int i = 0; i < 4; i++) { m_i[i] = -1e30f; l_i[i] = 0.f; }
#pragma unroll
    for (int p = 0; p < 2; p++)
#pragma unroll
        for (int c = 0; c < 4; c++) accO2[p][c] = 0ull;

    for (int kt = 0; kt < SEQ / 64; kt++) {
        __syncthreads();   // smem free (prev PV done; iter0: Q STS ordered below)
#pragma unroll
        for (int p = 0; p < 4; p++) {
            const int r = lrow + p * 16;
            Kt[lc4 + 0][r] = kreg[p].x; Kt[lc4 + 1][r] = kreg[p].y;
            Kt[lc4 + 2][r] = kreg[p].z; Kt[lc4 + 3][r] = kreg[p].w;
            *(float4*)&Vs[r][lc4] = vreg[p];
        }
        __syncthreads();

        if (kt + 1 < SEQ / 64) {   // prefetch next K/V (overlaps S compute)
            const int k0n = (kt + 1) * 64;
#pragma unroll
            for (int p = 0; p < 4; p++) {
                const int r = lrow + p * 16;
                kreg[p] = *(const float4*)&qkv[(k0n + r) * TDM + DM + h * DH + lc4];
                vreg[p] = *(const float4*)&qkv[(k0n + r) * TDM + 2 * DM + h * DH + lc4];
            }
        }

        // ---- S = Q K^T (f32x2, rows paired) ----
        ull s2[2][4];
#pragma unroll
        for (int p = 0; p < 2; p++)
#pragma unroll
            for (int j = 0; j < 4; j++) s2[p][j] = 0ull;

#pragma unroll 8
        for (int d = 0; d < DH; d++) {
            float4 q4 = *(const float4*)&Qt[d][ty * 4];
            float4 k4 = *(const float4*)&Kt[d][tx * 4];
            ull q2[2];
            q2[0] = pk2(q4.x, q4.y); q2[1] = pk2(q4.z, q4.w);
            ull kd[4];
            kd[0] = pk2(k4.x, k4.x); kd[1] = pk2(k4.y, k4.y);
            kd[2] = pk2(k4.z, k4.z); kd[3] = pk2(k4.w, k4.w);
#pragma unroll
            for (int p = 0; p < 2; p++)
#pragma unroll
                for (int j = 0; j < 4; j++)
                    FMA2(s2[p][j], q2[p], kd[j]);
        }

        // unpack, scale + bias
        float s[4][4];
#pragma unroll
        for (int j = 0; j < 4; j++) {
            upk2(s2[0][j], s[0][j], s[1][j]);
            upk2(s2[1][j], s[2][j], s[3][j]);
        }
        const int k0 = kt * 64;
#pragma unroll
        for (int i = 0; i < 4; i++) {
            const int qg = q0 + ty * 4 + i;
#pragma unroll
            for (int j = 0; j < 4; j++) {
                int dd = (k0 + tx * 4 + j) - qg;
                dd = dd < 0 ? -dd : dd;
                if (dd > MAXD - 1) dd = MAXD - 1;
                s[i][j] = fmaf(s[i][j], 0.125f, bias_s[dd]);
            }
        }

        // ---- online softmax ----
        float fac[4];
#pragma unroll
        for (int i = 0; i < 4; i++) {
            float mx = fmaxf(fmaxf(s[i][0], s[i][1]), fmaxf(s[i][2], s[i][3]));
#pragma unroll
            for (int o = 8; o >= 1; o >>= 1)
                mx = fmaxf(mx, __shfl_xor_sync(0xffffffffu, mx, o));
            float mnew = fmaxf(m_i[i], mx);
            fac[i] = __expf(m_i[i] - mnew);
            m_i[i] = mnew;
        }
#pragma unroll
        for (int i = 0; i < 4; i++) {
            float sum = 0.f;
#pragma unroll
            for (int j = 0; j < 4; j++) {
                s[i][j] = __expf(s[i][j] - m_i[i]);
                sum += s[i][j];
            }
#pragma unroll
            for (int o = 8; o >= 1; o >>= 1)
                sum += __shfl_xor_sync(0xffffffffu, sum, o);
            l_i[i] = l_i[i] * fac[i] + sum;
        }
        {
            ull f0 = pk2(fac[0], fac[1]);
            ull f1 = pk2(fac[2], fac[3]);
#pragma unroll
            for (int c = 0; c < 4; c++) { MUL2(accO2[0][c], f0); MUL2(accO2[1][c], f1); }
        }

        __syncthreads();   // all S reads of Kt done before aliasing as Pt
#pragma unroll
        for (int i = 0; i < 4; i++)
#pragma unroll
            for (int j = 0; j < 4; j++)
                Kt[tx * 4 + j][ty * 4 + i] = s[i][j];   // Pt[key][row]
        __syncthreads();

        // ---- O += P V (f32x2, rows paired) ----
#pragma unroll 8
        for (int j = 0; j < 64; j++) {
            float4 p4 = *(const float4*)&Kt[j][ty * 4];   // Pt[j][rows]
            float4 v4 = *(const float4*)&Vs[j][tx * 4];
            ull p2[2];
            p2[0] = pk2(p4.x, p4.y); p2[1] = pk2(p4.z, p4.w);
            ull vd[4];
            vd[0] = pk2(v4.x, v4.x); vd[1] = pk2(v4.y, v4.y);
            vd[2] = pk2(v4.z, v4.z); vd[3] = pk2(v4.w, v4.w);
#pragma unroll
            for (int p = 0; p < 2; p++)
#pragma unroll
                for (int c = 0; c < 4; c++)
                    FMA2(accO2[p][c], p2[p], vd[c]);
        }
    }

    // epilogue: unpack row pairs, normalize, store
#pragma unroll
    for (int p = 0; p < 2; p++) {
        float lo[4], hi[4];
#pragma unroll
        for (int c = 0; c < 4; c++) upk2(accO2[p][c], lo[c], hi[c]);
        const float inv0 = 1.f / l_i[2 * p];
        const float inv1 = 1.f / l_i[2 * p + 1];
        const int r0 = q0 + ty * 4 + 2 * p;
        *(float4*)&out[(ull)r0 * DM + h * DH + tx * 4] =
            make_float4(lo[0] * inv0, lo[1] * inv0, lo[2] * inv0, lo[3] * inv0);
        *(float4*)&out[(ull)(r0 + 1) * DM + h * DH + tx * 4] =
            make_float4(hi[0] * inv1, hi[1] * inv1, hi[2] * inv1, hi[3] * inv1);
    }
}

// ---------------------------------------------------------------------------
extern "C" void kernel_launch(void* const* d_in, const int* in_sizes, int n_in,
                              void* d_out, int out_size) {
    const float* x        = (const float*)d_in[0];
    const float* w_qkv    = (const float*)d_in[1];
    const float* w_out    = (const float*)d_in[2];
    const float* rel_bias = (const float*)d_in[3];
    float* out = (float*)d_out;

    float *qkv = nullptr, *attn = nullptr;
    cudaGetSymbolAddress((void**)&qkv,  g_qkv);
    cudaGetSymbolAddress((void**)&attn, g_attn);

    cudaFuncSetAttribute(attn_kernel, cudaFuncAttributeMaxDynamicSharedMemorySize,
                         ATTN_SMEM);

    // 1) qkv = x @ w_qkv
    gemm_f2<<<dim3(TDM / 128, SEQ / 128), 256>>>(x, w_qkv, qkv, SEQ, TDM, DM);

    // 2) attention
    attn_kernel<<<dim3(SEQ / 64, NH), 256, ATTN_SMEM>>>(qkv, rel_bias, attn);

    // 3) out = attn @ w_out
    gemm_f2<<<dim3(DM / 128, SEQ / 128), 256>>>(attn, w_out, out, SEQ, DM, DM);
}

// round 4
// speedup vs baseline: 1.3392x; 1.1739x over previous
#include <cuda_runtime.h>
#include <cuda_bf16.h>
#include <cstdint>
#include <math.h>

#define SEQ  2048
#define DM   1024
#define TDM  3072
#define NH   16
#define DH   64
#define MAXD 128

typedef unsigned long long ull;

// ---------------- scratch ---------------------------------------------------
__device__ float g_qkv[SEQ * TDM];   // [s][3*d_model]
__device__ float g_attn[SEQ * DM];   // [s][h*64+d]

// ---------------- helpers ---------------------------------------------------
__device__ __forceinline__ uint32_t smem_u32(const void* p) {
    uint32_t a;
    asm("{ .reg .u64 t; cvta.to.shared.u64 t, %1; cvt.u32.u64 %0, t; }" : "=r"(a) : "l"(p));
    return a;
}
__device__ __forceinline__ void ldsm_x4(uint32_t& r0, uint32_t& r1, uint32_t& r2,
                                        uint32_t& r3, uint32_t addr) {
    asm volatile("ldmatrix.sync.aligned.m8n8.x4.shared.b16 {%0,%1,%2,%3}, [%4];"
                 : "=r"(r0), "=r"(r1), "=r"(r2), "=r"(r3) : "r"(addr));
}
__device__ __forceinline__ void ldsm_x4t(uint32_t& r0, uint32_t& r1, uint32_t& r2,
                                         uint32_t& r3, uint32_t addr) {
    asm volatile("ldmatrix.sync.aligned.m8n8.x4.trans.shared.b16 {%0,%1,%2,%3}, [%4];"
                 : "=r"(r0), "=r"(r1), "=r"(r2), "=r"(r3) : "r"(addr));
}
__device__ __forceinline__ void mma16816(float* d, const uint32_t* a, const uint32_t* b) {
    asm volatile("mma.sync.aligned.m16n8k16.row.col.f32.bf16.bf16.f32 "
                 "{%0,%1,%2,%3}, {%4,%5,%6,%7}, {%8,%9}, {%0,%1,%2,%3};"
                 : "+f"(d[0]), "+f"(d[1]), "+f"(d[2]), "+f"(d[3])
                 : "r"(a[0]), "r"(a[1]), "r"(a[2]), "r"(a[3]), "r"(b[0]), "r"(b[1]));
}

// f32x2 helpers for the attention kernel
__device__ __forceinline__ ull pk2(float x, float y) {
    ull d;
    asm("mov.b64 %0, {%1, %2};" : "=l"(d) : "f"(x), "f"(y));
    return d;
}
__device__ __forceinline__ void upk2(ull d, float& x, float& y) {
    asm("mov.b64 {%0, %1}, %2;" : "=f"(x), "=f"(y) : "l"(d));
}
#define FMA2(c, a, b) asm("fma.rn.f32x2 %0, %1, %2, %0;" : "+l"(c) : "l"(a), "l"(b))
#define MUL2(c, a)    asm("mul.rn.f32x2 %0, %0, %1;"     : "+l"(c) : "l"(a))

// ---------------------------------------------------------------------------
// Split-bf16 mma.sync GEMM: C[M,N] = A[M,K] @ B[K,N]  (fp32 in/out).
// CTA 128x128, BK=32, 256 threads = 8 warps (4 warp_m x 2 warp_n), warp 32x64.
// 3-term split: C = Ahi*Bhi + Ahi*Blo + Alo*Bhi  (bf16 ops, fp32 accum).
// ---------------------------------------------------------------------------
#define SA 40                      // A smem row stride (bf16 elems): 32 + 8 pad
#define SB 136                     // B smem row stride: 128 + 8 pad
#define A_TILE_B (128 * SA * 2)    // 10240 B per term
#define B_TILE_B (32 * SB * 2)     // 8704 B per term
#define STAGE_B  (2 * A_TILE_B + 2 * B_TILE_B)   // 37888 B
#define GSMEM    (2 * STAGE_B)                   // 75776 B

__global__ __launch_bounds__(256)
void gemm_mma(const float* __restrict__ A, const float* __restrict__ B,
              float* __restrict__ C, int M, int N, int K) {
    extern __shared__ char smem[];
    const int tid  = threadIdx.x;
    const int lane = tid & 31;
    const int wid  = tid >> 5;
    const int wm   = wid & 3;      // warp row (32 rows each)
    const int wn   = wid >> 2;     // warp col (64 cols each)
    const int bm = blockIdx.y * 128;
    const int bn = blockIdx.x * 128;

    // gmem load mapping (fp32)
    const int ar = tid >> 1;             // 0..127 (A row)
    const int ak = (tid & 1) * 16;       // A k-half
    const int br = tid >> 3;             // 0..31  (B k-row)
    const int bc = (tid & 7) * 16;       // B n-offset

    const float* Ap = A + (ull)(bm + ar) * K + ak;
    const float* Bp = B + (ull)br * N + bn + bc;

    float4 areg[4], breg[4];
#pragma unroll
    for (int i = 0; i < 4; i++) {
        areg[i] = *(const float4*)(Ap + i * 4);
        breg[i] = *(const float4*)(Bp + i * 4);
    }

    float acc[2][8][4];
#pragma unroll
    for (int mt = 0; mt < 2; mt++)
#pragma unroll
        for (int nt = 0; nt < 8; nt++)
#pragma unroll
            for (int e = 0; e < 4; e++) acc[mt][nt][e] = 0.f;

    const uint32_t smem_b = smem_u32(smem);
    const int NT = K / 32;

    for (int t = 0; t < NT; t++) {
        const uint32_t stg = smem_b + (t & 1) * STAGE_B;
        // ---- convert + STS (hi/lo split) ----
        {
            __nv_bfloat162* Ahi = (__nv_bfloat162*)(smem + (t & 1) * STAGE_B);
            __nv_bfloat162* Alo = (__nv_bfloat162*)((char*)Ahi + A_TILE_B);
            __nv_bfloat162* Bhi = (__nv_bfloat162*)((char*)Ahi + 2 * A_TILE_B);
            __nv_bfloat162* Blo = (__nv_bfloat162*)((char*)Bhi + B_TILE_B);
#pragma unroll
            for (int i = 0; i < 4; i++) {
                float4 v = areg[i];
                __nv_bfloat162 h, l;
                h.x = __float2bfloat16_rn(v.x); h.y = __float2bfloat16_rn(v.y);
                l.x = __float2bfloat16_rn(v.x - __bfloat162float(h.x));
                l.y = __float2bfloat16_rn(v.y - __bfloat162float(h.y));
                Ahi[(ar * SA + ak + i * 4) >> 1] = h;
                Alo[(ar * SA + ak + i * 4) >> 1] = l;
                h.x = __float2bfloat16_rn(v.z); h.y = __float2bfloat16_rn(v.w);
                l.x = __float2bfloat16_rn(v.z - __bfloat162float(h.x));
                l.y = __float2bfloat16_rn(v.w - __bfloat162float(h.y));
                Ahi[(ar * SA + ak + i * 4 + 2) >> 1] = h;
                Alo[(ar * SA + ak + i * 4 + 2) >> 1] = l;

                float4 w = breg[i];
                h.x = __float2bfloat16_rn(w.x); h.y = __float2bfloat16_rn(w.y);
                l.x = __float2bfloat16_rn(w.x - __bfloat162float(h.x));
                l.y = __float2bfloat16_rn(w.y - __bfloat162float(h.y));
                Bhi[(br * SB + bc + i * 4) >> 1] = h;
                Blo[(br * SB + bc + i * 4) >> 1] = l;
                h.x = __float2bfloat16_rn(w.z); h.y = __float2bfloat16_rn(w.w);
                l.x = __float2bfloat16_rn(w.z - __bfloat162float(h.x));
                l.y = __float2bfloat16_rn(w.w - __bfloat162float(h.y));
                Bhi[(br * SB + bc + i * 4 + 2) >> 1] = h;
                Blo[(br * SB + bc + i * 4 + 2) >> 1] = l;
            }
        }
        __syncthreads();

        if (t + 1 < NT) {   // prefetch next fp32 tile (hidden under mma phase)
#pragma unroll
            for (int i = 0; i < 4; i++) {
                areg[i] = *(const float4*)(Ap + (t + 1) * 32 + i * 4);
                breg[i] = *(const float4*)(Bp + (ull)(t + 1) * 32 * N + i * 4);
            }
        }

        // ---- compute: 2 k16 sub-steps ----
        const uint32_t uAhi = stg;
        const uint32_t uAlo = stg + A_TILE_B;
        const uint32_t uBhi = stg + 2 * A_TILE_B;
        const uint32_t uBlo = uBhi + B_TILE_B;
#pragma unroll
        for (int ks = 0; ks < 2; ks++) {
            const int k0 = ks * 16;
            uint32_t afh[2][4], afl[2][4];
#pragma unroll
            for (int mt = 0; mt < 2; mt++) {
                const int row = wm * 32 + mt * 16 + (lane & 15);
                const int col = k0 + ((lane >> 4) << 3);
                const uint32_t off = (uint32_t)(row * SA + col) * 2;
                ldsm_x4(afh[mt][0], afh[mt][1], afh[mt][2], afh[mt][3], uAhi + off);
                ldsm_x4(afl[mt][0], afl[mt][1], afl[mt][2], afl[mt][3], uAlo + off);
            }
#pragma unroll
            for (int g = 0; g < 4; g++) {
                uint32_t bh[4], bl[4];
                const int row = k0 + (lane & 15);
                const int col = wn * 64 + g * 16 + ((lane >> 4) << 3);
                const uint32_t off = (uint32_t)(row * SB + col) * 2;
                ldsm_x4t(bh[0], bh[1], bh[2], bh[3], uBhi + off);
                ldsm_x4t(bl[0], bl[1], bl[2], bl[3], uBlo + off);
#pragma unroll
                for (int mt = 0; mt < 2; mt++) {
                    mma16816(acc[mt][2 * g],     afh[mt], &bh[0]);
                    mma16816(acc[mt][2 * g],     afh[mt], &bl[0]);
                    mma16816(acc[mt][2 * g],     afl[mt], &bh[0]);
                    mma16816(acc[mt][2 * g + 1], afh[mt], &bh[2]);
                    mma16816(acc[mt][2 * g + 1], afh[mt], &bl[2]);
                    mma16816(acc[mt][2 * g + 1], afl[mt], &bh[2]);
                }
            }
        }
        __syncthreads();
    }

    // ---- epilogue: fragment -> gmem ----
    const int group = lane >> 2;
    const int tq = lane & 3;
#pragma unroll
    for (int mt = 0; mt < 2; mt++) {
#pragma unroll
        for (int nt = 0; nt < 8; nt++) {
            const int row = bm + wm * 32 + mt * 16 + group;
            const int col = bn + wn * 64 + nt * 8 + tq * 2;
            *(float2*)&C[(ull)row * N + col] =
                make_float2(acc[mt][nt][0], acc[mt][nt][1]);
            *(float2*)&C[(ull)(row + 8) * N + col] =
                make_float2(acc[mt][nt][2], acc[mt][nt][3]);
        }
    }
}

// ---------------------------------------------------------------------------
// Flash attention with relative-position bias, FFMA2 inner loops (R3 kernel).
// ---------------------------------------------------------------------------
#define AST 68
#define ATTN_SMEM (3 * 64 * AST * 4)

__global__ __launch_bounds__(256, 2)
void attn_kernel(const float* __restrict__ qkv, const float* __restrict__ rel_bias,
                 float* __restrict__ out) {
    extern __shared__ float sm[];
    float (*Qt)[AST] = (float(*)[AST])sm;                   // Qt[d][row]
    float (*Kt)[AST] = (float(*)[AST])(sm + 64 * AST);      // Kt[d][key]; aliased Pt[key][row]
    float (*Vs)[AST] = (float(*)[AST])(sm + 2 * 64 * AST);  // Vs[key][d]
    __shared__ float bias_s[MAXD];

    const int tid = threadIdx.x;
    const int tx = tid & 15;
    const int ty = tid >> 4;
    const int h  = blockIdx.y;
    const int q0 = blockIdx.x * 64;

    if (tid < MAXD) bias_s[tid] = rel_bias[tid * NH + h];

    const int lrow = tid >> 4;
    const int lc4  = (tid & 15) << 2;

#pragma unroll
    for (int p = 0; p < 4; p++) {
        const int r = lrow + p * 16;
        float4 v = *(const float4*)&qkv[(q0 + r) * TDM + h * DH + lc4];
        Qt[lc4 + 0][r] = v.x; Qt[lc4 + 1][r] = v.y;
        Qt[lc4 + 2][r] = v.z; Qt[lc4 + 3][r] = v.w;
    }

    float4 kreg[4], vreg[4];
#pragma unroll
    for (int p = 0; p < 4; p++) {
        const int r = lrow + p * 16;
        kreg[p] = *(const float4*)&qkv[r * TDM + DM + h * DH + lc4];
        vreg[p] = *(const float4*)&qkv[r * TDM + 2 * DM + h * DH + lc4];
    }

    float m_i[4], l_i[4];
    ull accO2[2][4];
#pragma unroll
    for (int i = 0; i < 4; i++) { m_i[i] = -1e30f; l_i[i] = 0.f; }
#pragma unroll
    for (int p = 0; p < 2; p++)
#pragma unroll
        for (int c = 0; c < 4; c++) accO2[p][c] = 0ull;

    for (int kt = 0; kt < SEQ / 64; kt++) {
        __syncthreads();
#pragma unroll
        for (int p = 0; p < 4; p++) {
            const int r = lrow + p * 16;
            Kt[lc4 + 0][r] = kreg[p].x; Kt[lc4 + 1][r] = kreg[p].y;
            Kt[lc4 + 2][r] = kreg[p].z; Kt[lc4 + 3][r] = kreg[p].w;
            *(float4*)&Vs[r][lc4] = vreg[p];
        }
        __syncthreads();

        if (kt + 1 < SEQ / 64) {
            const int k0n = (kt + 1) * 64;
#pragma unroll
            for (int p = 0; p < 4; p++) {
                const int r = lrow + p * 16;
                kreg[p] = *(const float4*)&qkv[(k0n + r) * TDM + DM + h * DH + lc4];
                vreg[p] = *(const float4*)&qkv[(k0n + r) * TDM + 2 * DM + h * DH + lc4];
            }
        }

        ull s2[2][4];
#pragma unroll
        for (int p = 0; p < 2; p++)
#pragma unroll
            for (int j = 0; j < 4; j++) s2[p][j] = 0ull;

#pragma unroll 8
        for (int d = 0; d < DH; d++) {
            float4 q4 = *(const float4*)&Qt[d][ty * 4];
            float4 k4 = *(const float4*)&Kt[d][tx * 4];
            ull q2[2];
            q2[0] = pk2(q4.x, q4.y); q2[1] = pk2(q4.z, q4.w);
            ull kd[4];
            kd[0] = pk2(k4.x, k4.x); kd[1] = pk2(k4.y, k4.y);
            kd[2] = pk2(k4.z, k4.z); kd[3] = pk2(k4.w, k4.w);
#pragma unroll
            for (int p = 0; p < 2; p++)
#pragma unroll
                for (int j = 0; j < 4; j++)
                    FMA2(s2[p][j], q2[p], kd[j]);
        }

        float s[4][4];
#pragma unroll
        for (int j = 0; j < 4; j++) {
            upk2(s2[0][j], s[0][j], s[1][j]);
            upk2(s2[1][j], s[2][j], s[3][j]);
        }
        const int k0 = kt * 64;
#pragma unroll
        for (int i = 0; i < 4; i++) {
            const int qg = q0 + ty * 4 + i;
#pragma unroll
            for (int j = 0; j < 4; j++) {
                int dd = (k0 + tx * 4 + j) - qg;
                dd = dd < 0 ? -dd : dd;
                if (dd > MAXD - 1) dd = MAXD - 1;
                s[i][j] = fmaf(s[i][j], 0.125f, bias_s[dd]);
            }
        }

        float fac[4];
#pragma unroll
        for (int i = 0; i < 4; i++) {
            float mx = fmaxf(fmaxf(s[i][0], s[i][1]), fmaxf(s[i][2], s[i][3]));
#pragma unroll
            for (int o = 8; o >= 1; o >>= 1)
                mx = fmaxf(mx, __shfl_xor_sync(0xffffffffu, mx, o));
            float mnew = fmaxf(m_i[i], mx);
            fac[i] = __expf(m_i[i] - mnew);
            m_i[i] = mnew;
        }
#pragma unroll
        for (int i = 0; i < 4; i++) {
            float sum = 0.f;
#pragma unroll
            for (int j = 0; j < 4; j++) {
                s[i][j] = __expf(s[i][j] - m_i[i]);
                sum += s[i][j];
            }
#pragma unroll
            for (int o = 8; o >= 1; o >>= 1)
                sum += __shfl_xor_sync(0xffffffffu, sum, o);
            l_i[i] = l_i[i] * fac[i] + sum;
        }
        {
            ull f0 = pk2(fac[0], fac[1]);
            ull f1 = pk2(fac[2], fac[3]);
#pragma unroll
            for (int c = 0; c < 4; c++) { MUL2(accO2[0][c], f0); MUL2(accO2[1][c], f1); }
        }

        __syncthreads();
#pragma unroll
        for (int i = 0; i < 4; i++)
#pragma unroll
            for (int j = 0; j < 4; j++)
                Kt[tx * 4 + j][ty * 4 + i] = s[i][j];
        __syncthreads();

#pragma unroll 8
        for (int j = 0; j < 64; j++) {
            float4 p4 = *(const float4*)&Kt[j][ty * 4];
            float4 v4 = *(const float4*)&Vs[j][tx * 4];
            ull p2[2];
            p2[0] = pk2(p4.x, p4.y); p2[1] = pk2(p4.z, p4.w);
            ull vd[4];
            vd[0] = pk2(v4.x, v4.x); vd[1] = pk2(v4.y, v4.y);
            vd[2] = pk2(v4.z, v4.z); vd[3] = pk2(v4.w, v4.w);
#pragma unroll
            for (int p = 0; p < 2; p++)
#pragma unroll
                for (int c = 0; c < 4; c++)
                    FMA2(accO2[p][c], p2[p], vd[c]);
        }
    }

#pragma unroll
    for (int p = 0; p < 2; p++) {
        float lo[4], hi[4];
#pragma unroll
        for (int c = 0; c < 4; c++) upk2(accO2[p][c], lo[c], hi[c]);
        const float inv0 = 1.f / l_i[2 * p];
        const float inv1 = 1.f / l_i[2 * p + 1];
        const int r0 = q0 + ty * 4 + 2 * p;
        *(float4*)&out[(ull)r0 * DM + h * DH + tx * 4] =
            make_float4(lo[0] * inv0, lo[1] * inv0, lo[2] * inv0, lo[3] * inv0);
        *(float4*)&out[(ull)(r0 + 1) * DM + h * DH + tx * 4] =
            make_float4(hi[0] * inv1, hi[1] * inv1, hi[2] * inv1, hi[3] * inv1);
    }
}

// ---------------------------------------------------------------------------
extern "C" void kernel_launch(void* const* d_in, const int* in_sizes, int n_in,
                              void* d_out, int out_size) {
    const float* x        = (const float*)d_in[0];
    const float* w_qkv    = (const float*)d_in[1];
    const float* w_out    = (const float*)d_in[2];
    const float* rel_bias = (const float*)d_in[3];
    float* out = (float*)d_out;

    float *qkv = nullptr, *attn = nullptr;
    cudaGetSymbolAddress((void**)&qkv,  g_qkv);
    cudaGetSymbolAddress((void**)&attn, g_attn);

    cudaFuncSetAttribute(gemm_mma, cudaFuncAttributeMaxDynamicSharedMemorySize, GSMEM);
    cudaFuncSetAttribute(attn_kernel, cudaFuncAttributeMaxDynamicSharedMemorySize,
                         ATTN_SMEM);

    // 1) qkv = x @ w_qkv   (split-bf16 mma.sync)
    gemm_mma<<<dim3(TDM / 128, SEQ / 128), 256, GSMEM>>>(x, w_qkv, qkv, SEQ, TDM, DM);

    // 2) attention (FFMA2 flash)
    attn_kernel<<<dim3(SEQ / 64, NH), 256, ATTN_SMEM>>>(qkv, rel_bias, attn);

    // 3) out = attn @ w_out  (split-bf16 mma.sync)
    gemm_mma<<<dim3(DM / 128, SEQ / 128), 256, GSMEM>>>(attn, w_out, out, SEQ, DM, DM);
}

// round 6
// speedup vs baseline: 2.3505x; 1.7551x over previous
#include <cuda_runtime.h>
#include <cuda_bf16.h>
#include <cstdint>
#include <math.h>

#define SEQ  2048
#define DM   1024
#define TDM  3072
#define NH   16
#define DH   64
#define MAXD 128

typedef unsigned long long ull;

// ---------------- scratch ---------------------------------------------------
__device__ float g_qkv[SEQ * TDM];   // [s][3*d_model]
__device__ float g_attn[SEQ * DM];   // [s][h*64+d]

// ---------------- helpers ---------------------------------------------------
__device__ __forceinline__ uint32_t smem_u32(const void* p) {
    uint32_t a;
    asm("{ .reg .u64 t; cvta.to.shared.u64 t, %1; cvt.u32.u64 %0, t; }" : "=r"(a) : "l"(p));
    return a;
}
__device__ __forceinline__ void ldsm_x4(uint32_t& r0, uint32_t& r1, uint32_t& r2,
                                        uint32_t& r3, uint32_t addr) {
    asm volatile("ldmatrix.sync.aligned.m8n8.x4.shared.b16 {%0,%1,%2,%3}, [%4];"
                 : "=r"(r0), "=r"(r1), "=r"(r2), "=r"(r3) : "r"(addr));
}
__device__ __forceinline__ void ldsm_x4t(uint32_t& r0, uint32_t& r1, uint32_t& r2,
                                         uint32_t& r3, uint32_t addr) {
    asm volatile("ldmatrix.sync.aligned.m8n8.x4.trans.shared.b16 {%0,%1,%2,%3}, [%4];"
                 : "=r"(r0), "=r"(r1), "=r"(r2), "=r"(r3) : "r"(addr));
}
__device__ __forceinline__ void mma16816(float* d, const uint32_t* a, const uint32_t* b) {
    asm volatile("mma.sync.aligned.m16n8k16.row.col.f32.bf16.bf16.f32 "
                 "{%0,%1,%2,%3}, {%4,%5,%6,%7}, {%8,%9}, {%0,%1,%2,%3};"
                 : "+f"(d[0]), "+f"(d[1]), "+f"(d[2]), "+f"(d[3])
                 : "r"(a[0]), "r"(a[1]), "r"(a[2]), "r"(a[3]), "r"(b[0]), "r"(b[1]));
}
__device__ __forceinline__ uint32_t bf16x2_of(float lo, float hi) {
    uint32_t r;
    asm("cvt.rn.bf16x2.f32 %0, %1, %2;" : "=r"(r) : "f"(hi), "f"(lo));
    return r;
}
// pack (x,y) into hi-bf16x2 and residual-lo-bf16x2
__device__ __forceinline__ void pack_hilo(float x, float y, uint32_t& ph, uint32_t& pl) {
    __nv_bfloat16 hx = __float2bfloat16_rn(x);
    __nv_bfloat16 hy = __float2bfloat16_rn(y);
    float fx = __bfloat162float(hx), fy = __bfloat162float(hy);
    ph = ((uint32_t)__bfloat16_as_ushort(hy) << 16) | (uint32_t)__bfloat16_as_ushort(hx);
    pl = bf16x2_of(x - fx, y - fy);
}
// split a float4 into hi/lo bf16x2 pairs and store at [row][col..col+3]
__device__ __forceinline__ void sts_split4(char* hi_base, char* lo_base,
                                           int row, int col, int stride, float4 v) {
    uint32_t h0, l0, h1, l1;
    pack_hilo(v.x, v.y, h0, l0);
    pack_hilo(v.z, v.w, h1, l1);
    char* ph = hi_base + (row * stride + col) * 2;
    char* pl = lo_base + (row * stride + col) * 2;
    *(uint32_t*)(ph)     = h0;
    *(uint32_t*)(ph + 4) = h1;
    *(uint32_t*)(pl)     = l0;
    *(uint32_t*)(pl + 4) = l1;
}

// ---------------------------------------------------------------------------
// Split-bf16 mma.sync GEMM (validated R4): C[M,N] = A[M,K] @ B[K,N].
// ---------------------------------------------------------------------------
#define SA 40
#define SB 136
#define A_TILE_B (128 * SA * 2)
#define B_TILE_B (32 * SB * 2)
#define STAGE_B  (2 * A_TILE_B + 2 * B_TILE_B)
#define GSMEM    (2 * STAGE_B)

__global__ __launch_bounds__(256)
void gemm_mma(const float* __restrict__ A, const float* __restrict__ B,
              float* __restrict__ C, int M, int N, int K) {
    extern __shared__ char smem[];
    const int tid  = threadIdx.x;
    const int lane = tid & 31;
    const int wid  = tid >> 5;
    const int wm   = wid & 3;
    const int wn   = wid >> 2;
    const int bm = blockIdx.y * 128;
    const int bn = blockIdx.x * 128;

    const int ar = tid >> 1;
    const int ak = (tid & 1) * 16;
    const int br = tid >> 3;
    const int bc = (tid & 7) * 16;

    const float* Ap = A + (ull)(bm + ar) * K + ak;
    const float* Bp = B + (ull)br * N + bn + bc;

    float4 areg[4], breg[4];
#pragma unroll
    for (int i = 0; i < 4; i++) {
        areg[i] = *(const float4*)(Ap + i * 4);
        breg[i] = *(const float4*)(Bp + i * 4);
    }

    float acc[2][8][4];
#pragma unroll
    for (int mt = 0; mt < 2; mt++)
#pragma unroll
        for (int nt = 0; nt < 8; nt++)
#pragma unroll
            for (int e = 0; e < 4; e++) acc[mt][nt][e] = 0.f;

    const uint32_t smem_b = smem_u32(smem);
    const int NT = K / 32;

    for (int t = 0; t < NT; t++) {
        const uint32_t stg = smem_b + (t & 1) * STAGE_B;
        {
            char* Ahi = smem + (t & 1) * STAGE_B;
            char* Alo = Ahi + A_TILE_B;
            char* Bhi = Ahi + 2 * A_TILE_B;
            char* Blo = Bhi + B_TILE_B;
#pragma unroll
            for (int i = 0; i < 4; i++) {
                sts_split4(Ahi, Alo, ar, ak + i * 4, SA, areg[i]);
                sts_split4(Bhi, Blo, br, bc + i * 4, SB, breg[i]);
            }
        }
        __syncthreads();

        if (t + 1 < NT) {
#pragma unroll
            for (int i = 0; i < 4; i++) {
                areg[i] = *(const float4*)(Ap + (t + 1) * 32 + i * 4);
                breg[i] = *(const float4*)(Bp + (ull)(t + 1) * 32 * N + i * 4);
            }
        }

        const uint32_t uAhi = stg;
        const uint32_t uAlo = stg + A_TILE_B;
        const uint32_t uBhi = stg + 2 * A_TILE_B;
        const uint32_t uBlo = uBhi + B_TILE_B;
#pragma unroll
        for (int ks = 0; ks < 2; ks++) {
            const int k0 = ks * 16;
            uint32_t afh[2][4], afl[2][4];
#pragma unroll
            for (int mt = 0; mt < 2; mt++) {
                const int row = wm * 32 + mt * 16 + (lane & 15);
                const int col = k0 + ((lane >> 4) << 3);
                const uint32_t off = (uint32_t)(row * SA + col) * 2;
                ldsm_x4(afh[mt][0], afh[mt][1], afh[mt][2], afh[mt][3], uAhi + off);
                ldsm_x4(afl[mt][0], afl[mt][1], afl[mt][2], afl[mt][3], uAlo + off);
            }
#pragma unroll
            for (int g = 0; g < 4; g++) {
                uint32_t bh[4], bl[4];
                const int row = k0 + (lane & 15);
                const int col = wn * 64 + g * 16 + ((lane >> 4) << 3);
                const uint32_t off = (uint32_t)(row * SB + col) * 2;
                ldsm_x4t(bh[0], bh[1], bh[2], bh[3], uBhi + off);
                ldsm_x4t(bl[0], bl[1], bl[2], bl[3], uBlo + off);
#pragma unroll
                for (int mt = 0; mt < 2; mt++) {
                    mma16816(acc[mt][2 * g],     afh[mt], &bh[0]);
                    mma16816(acc[mt][2 * g],     afh[mt], &bl[0]);
                    mma16816(acc[mt][2 * g],     afl[mt], &bh[0]);
                    mma16816(acc[mt][2 * g + 1], afh[mt], &bh[2]);
                    mma16816(acc[mt][2 * g + 1], afh[mt], &bl[2]);
                    mma16816(acc[mt][2 * g + 1], afl[mt], &bh[2]);
                }
            }
        }
        __syncthreads();
    }

    const int group = lane >> 2;
    const int tq = lane & 3;
#pragma unroll
    for (int mt = 0; mt < 2; mt++) {
#pragma unroll
        for (int nt = 0; nt < 8; nt++) {
            const int row = bm + wm * 32 + mt * 16 + group;
            const int col = bn + wn * 64 + nt * 8 + tq * 2;
            *(float2*)&C[(ull)row * N + col] =
                make_float2(acc[mt][nt][0], acc[mt][nt][1]);
            *(float2*)&C[(ull)(row + 8) * N + col] =
                make_float2(acc[mt][nt][2], acc[mt][nt][3]);
        }
    }
}

// ---------------------------------------------------------------------------
// HMMA flash attention, split-bf16 3-term for S=QK^T and O=PV.
// Grid (SEQ/64, NH), 256 threads = 8 warps: wm = wid&3 (16 q-rows each),
// wn = wid>>2 (32-key half). Each warp holds partial O[16 x 64] over its keys;
// one cross-pair add at the end.
// ---------------------------------------------------------------------------
#define QSTR 72                    // bf16 elems per smem row (144 B)
#define OFF_QH 0
#define OFF_QL 9216
#define OFF_KH 18432
#define OFF_KL 27648
#define OFF_VH 36864
#define OFF_VL 46080
#define OFF_BIAS 55296
#define OFF_RM 55808               // float[2][64]
#define OFF_RS 56320               // float[2][64]
#define ATT_SMEM 56832
#define OFF_OEP OFF_KH             // epilogue f32 [64][68] aliases K region

__global__ __launch_bounds__(256)
void attn_mma(const float* __restrict__ qkv, const float* __restrict__ rel_bias,
              float* __restrict__ out) {
    extern __shared__ char sm[];
    const uint32_t sb = smem_u32(sm);
    const int tid  = threadIdx.x;
    const int lane = tid & 31;
    const int wid  = tid >> 5;
    const int wm   = wid & 3;
    const int wn   = wid >> 2;
    const int h  = blockIdx.y;
    const int q0 = blockIdx.x * 64;

    float* redM   = (float*)(sm + OFF_RM);
    float* redS   = (float*)(sm + OFF_RS);
    float* bias_s = (float*)(sm + OFF_BIAS);
    if (tid < MAXD) bias_s[tid] = rel_bias[tid * NH + h];

    const int grow = tid >> 2;          // 0..63
    const int gcol = (tid & 3) * 16;    // 0..48

    // Q tile: load fp32, split hi/lo into smem (once)
    {
        const float* Qp = qkv + (ull)(q0 + grow) * TDM + h * DH + gcol;
#pragma unroll
        for (int i = 0; i < 4; i++)
            sts_split4(sm + OFF_QH, sm + OFF_QL, grow, gcol + i * 4, QSTR,
                       *(const float4*)(Qp + i * 4));
    }

    // prefetch K/V tile 0
    float4 kreg[4], vreg[4];
    {
        const float* Kp = qkv + (ull)grow * TDM + DM + h * DH + gcol;
        const float* Vp = qkv + (ull)grow * TDM + 2 * DM + h * DH + gcol;
#pragma unroll
        for (int i = 0; i < 4; i++) {
            kreg[i] = *(const float4*)(Kp + i * 4);
            vreg[i] = *(const float4*)(Vp + i * 4);
        }
    }

    float m_a = -1e30f, m_b = -1e30f, l_a = 0.f, l_b = 0.f;
    float accO[8][4];
#pragma unroll
    for (int d = 0; d < 8; d++)
#pragma unroll
        for (int e = 0; e < 4; e++) accO[d][e] = 0.f;

    // ldsm address components
    const int qa_row   = wm * 16 + (lane & 15);
    const int qa_coff  = (lane >> 4) << 3;
    const int kb_key   = wn * 32 + ((lane >> 4) << 3) + (lane & 7);
    const int kb_coff  = ((lane >> 3) & 1) << 3;
    const int vb_key   = wn * 32 + (lane & 15);
    const int vb_coff  = (lane >> 4) << 3;
    const int rA = wm * 16 + (lane >> 2);   // local q row
    const int rB = rA + 8;
    const int qA = q0 + rA, qB = q0 + rB;   // global q rows

    for (int kt = 0; kt < SEQ / 64; kt++) {
        __syncthreads();
#pragma unroll
        for (int i = 0; i < 4; i++) {
            sts_split4(sm + OFF_KH, sm + OFF_KL, grow, gcol + i * 4, QSTR, kreg[i]);
            sts_split4(sm + OFF_VH, sm + OFF_VL, grow, gcol + i * 4, QSTR, vreg[i]);
        }
        __syncthreads();

        if (kt + 1 < SEQ / 64) {
            const ull r = (ull)((kt + 1) * 64 + grow) * TDM + h * DH + gcol;
#pragma unroll
            for (int i = 0; i < 4; i++) {
                kreg[i] = *(const float4*)(qkv + r + DM + i * 4);
                vreg[i] = *(const float4*)(qkv + r + 2 * DM + i * 4);
            }
        }

        // ---- S = Q K^T ----
        float sS[4][4];
#pragma unroll
        for (int f = 0; f < 4; f++)
#pragma unroll
            for (int e = 0; e < 4; e++) sS[f][e] = 0.f;

#pragma unroll
        for (int ks = 0; ks < 4; ks++) {
            const uint32_t qoff = (uint32_t)(qa_row * QSTR + ks * 16 + qa_coff) * 2;
            uint32_t qh[4], ql[4];
            ldsm_x4(qh[0], qh[1], qh[2], qh[3], sb + OFF_QH + qoff);
            ldsm_x4(ql[0], ql[1], ql[2], ql[3], sb + OFF_QL + qoff);
#pragma unroll
            for (int kg = 0; kg < 2; kg++) {
                const uint32_t koff =
                    (uint32_t)((kb_key + kg * 16) * QSTR + ks * 16 + kb_coff) * 2;
                uint32_t kh[4], kl[4];
                ldsm_x4(kh[0], kh[1], kh[2], kh[3], sb + OFF_KH + koff);
                ldsm_x4(kl[0], kl[1], kl[2], kl[3], sb + OFF_KL + koff);
                mma16816(sS[2 * kg],     qh, &kh[0]);
                mma16816(sS[2 * kg],     qh, &kl[0]);
                mma16816(sS[2 * kg],     ql, &kh[0]);
                mma16816(sS[2 * kg + 1], qh, &kh[2]);
                mma16816(sS[2 * kg + 1], qh, &kl[2]);
                mma16816(sS[2 * kg + 1], ql, &kh[2]);
            }
        }

        // ---- scale + relative bias ----
        const int kbase = kt * 64 + wn * 32 + (lane & 3) * 2;
#pragma unroll
        for (int f = 0; f < 4; f++) {
#pragma unroll
            for (int e = 0; e < 2; e++) {
                const int kg = kbase + f * 8 + e;
                int dA = kg - qA; dA = dA < 0 ? -dA : dA; if (dA > MAXD - 1) dA = MAXD - 1;
                int dB = kg - qB; dB = dB < 0 ? -dB : dB; if (dB > MAXD - 1) dB = MAXD - 1;
                sS[f][e]     = fmaf(sS[f][e],     0.125f, bias_s[dA]);
                sS[f][2 + e] = fmaf(sS[f][2 + e], 0.125f, bias_s[dB]);
            }
        }

        // ---- online softmax ----
        float mxA = fmaxf(fmaxf(sS[0][0], sS[0][1]), fmaxf(sS[1][0], sS[1][1]));
        mxA = fmaxf(mxA, fmaxf(fmaxf(sS[2][0], sS[2][1]), fmaxf(sS[3][0], sS[3][1])));
        float mxB = fmaxf(fmaxf(sS[0][2], sS[0][3]), fmaxf(sS[1][2], sS[1][3]));
        mxB = fmaxf(mxB, fmaxf(fmaxf(sS[2][2], sS[2][3]), fmaxf(sS[3][2], sS[3][3])));
        mxA = fmaxf(mxA, __shfl_xor_sync(0xffffffffu, mxA, 1));
        mxA = fmaxf(mxA, __shfl_xor_sync(0xffffffffu, mxA, 2));
        mxB = fmaxf(mxB, __shfl_xor_sync(0xffffffffu, mxB, 1));
        mxB = fmaxf(mxB, __shfl_xor_sync(0xffffffffu, mxB, 2));
        if ((lane & 3) == 0) { redM[wn * 64 + rA] = mxA; redM[wn * 64 + rB] = mxB; }
        __syncthreads();
        mxA = fmaxf(redM[rA], redM[64 + rA]);
        mxB = fmaxf(redM[rB], redM[64 + rB]);

        const float mnA = fmaxf(m_a, mxA), mnB = fmaxf(m_b, mxB);
        const float facA = __expf(m_a - mnA), facB = __expf(m_b - mnB);
        m_a = mnA; m_b = mnB;

        float sumA = 0.f, sumB = 0.f;
#pragma unroll
        for (int f = 0; f < 4; f++) {
#pragma unroll
            for (int e = 0; e < 2; e++) {
                sS[f][e]     = __expf(sS[f][e]     - m_a); sumA += sS[f][e];
                sS[f][2 + e] = __expf(sS[f][2 + e] - m_b); sumB += sS[f][2 + e];
            }
        }
        sumA += __shfl_xor_sync(0xffffffffu, sumA, 1);
        sumA += __shfl_xor_sync(0xffffffffu, sumA, 2);
        sumB += __shfl_xor_sync(0xffffffffu, sumB, 1);
        sumB += __shfl_xor_sync(0xffffffffu, sumB, 2);
        if ((lane & 3) == 0) { redS[wn * 64 + rA] = sumA; redS[wn * 64 + rB] = sumB; }
        __syncthreads();
        sumA = redS[rA] + redS[64 + rA];
        sumB = redS[rB] + redS[64 + rB];
        l_a = l_a * facA + sumA;
        l_b = l_b * facB + sumB;

#pragma unroll
        for (int d = 0; d < 8; d++) {
            accO[d][0] *= facA; accO[d][1] *= facA;
            accO[d][2] *= facB; accO[d][3] *= facB;
        }

        // ---- O += P V  (P from S registers) ----
#pragma unroll
        for (int ks2 = 0; ks2 < 2; ks2++) {
            uint32_t aH[4], aL[4];
            pack_hilo(sS[2 * ks2][0],     sS[2 * ks2][1],     aH[0], aL[0]);
            pack_hilo(sS[2 * ks2][2],     sS[2 * ks2][3],     aH[1], aL[1]);
            pack_hilo(sS[2 * ks2 + 1][0], sS[2 * ks2 + 1][1], aH[2], aL[2]);
            pack_hilo(sS[2 * ks2 + 1][2], sS[2 * ks2 + 1][3], aH[3], aL[3]);
            const int vrow = vb_key + ks2 * 16;
#pragma unroll
            for (int dg = 0; dg < 4; dg++) {
                const uint32_t voff =
                    (uint32_t)(vrow * QSTR + dg * 16 + vb_coff) * 2;
                uint32_t vh[4], vl[4];
                ldsm_x4t(vh[0], vh[1], vh[2], vh[3], sb + OFF_VH + voff);
                ldsm_x4t(vl[0], vl[1], vl[2], vl[3], sb + OFF_VL + voff);
                mma16816(accO[2 * dg],     aH, &vh[0]);
                mma16816(accO[2 * dg],     aH, &vl[0]);
                mma16816(accO[2 * dg],     aL, &vh[0]);
                mma16816(accO[2 * dg + 1], aH, &vh[2]);
                mma16816(accO[2 * dg + 1], aH, &vl[2]);
                mma16816(accO[2 * dg + 1], aL, &vh[2]);
            }
        }
    }

    // ---- epilogue: cross-pair add + normalize ----
    __syncthreads();
    float* Oep = (float*)(sm + OFF_OEP);   // [64][68]
    const int ecol = (lane & 3) * 2;
    if (wn == 1) {
#pragma unroll
        for (int d = 0; d < 8; d++) {
            *(float2*)&Oep[rA * 68 + d * 8 + ecol] = make_float2(accO[d][0], accO[d][1]);
            *(float2*)&Oep[rB * 68 + d * 8 + ecol] = make_float2(accO[d][2], accO[d][3]);
        }
    }
    __syncthreads();
    if (wn == 0) {
        const float invA = 1.f / l_a, invB = 1.f / l_b;
#pragma unroll
        for (int d = 0; d < 8; d++) {
            float2 pA = *(float2*)&Oep[rA * 68 + d * 8 + ecol];
            float2 pB = *(float2*)&Oep[rB * 68 + d * 8 + ecol];
            *(float2*)&out[(ull)qA * DM + h * DH + d * 8 + ecol] =
                make_float2((accO[d][0] + pA.x) * invA, (accO[d][1] + pA.y) * invA);
            *(float2*)&out[(ull)qB * DM + h * DH + d * 8 + ecol] =
                make_float2((accO[d][2] + pB.x) * invB, (accO[d][3] + pB.y) * invB);
        }
    }
}

// ---------------------------------------------------------------------------
extern "C" void kernel_launch(void* const* d_in, const int* in_sizes, int n_in,
                              void* d_out, int out_size) {
    const float* x        = (const float*)d_in[0];
    const float* w_qkv    = (const float*)d_in[1];
    const float* w_out    = (const float*)d_in[2];
    const float* rel_bias = (const float*)d_in[3];
    float* out = (float*)d_out;

    float *qkv = nullptr, *attn = nullptr;
    cudaGetSymbolAddress((void**)&qkv,  g_qkv);
    cudaGetSymbolAddress((void**)&attn, g_attn);

    cudaFuncSetAttribute(gemm_mma, cudaFuncAttributeMaxDynamicSharedMemorySize, GSMEM);
    cudaFuncSetAttribute(attn_mma, cudaFuncAttributeMaxDynamicSharedMemorySize, ATT_SMEM);

    // 1) qkv = x @ w_qkv
    gemm_mma<<<dim3(TDM / 128, SEQ / 128), 256, GSMEM>>>(x, w_qkv, qkv, SEQ, TDM, DM);

    // 2) attention (HMMA flash)
    attn_mma<<<dim3(SEQ / 64, NH), 256, ATT_SMEM>>>(qkv, rel_bias, attn);

    // 3) out = attn @ w_out
    gemm_mma<<<dim3(DM / 128, SEQ / 128), 256, GSMEM>>>(attn, w_out, out, SEQ, DM, DM);
}